// round 1
// baseline (speedup 1.0000x reference)
#include <cuda_runtime.h>
#include <math.h>

// ---------------- problem constants ----------------
#define B_      128
#define STREAM_ 512
#define INCH    4
#define EXTRA_  5
#define G_      2
#define STEP_   16
#define C_      10          // INCH + 1 + EXTRA
#define SIGC    1110        // C + C^2 + C^3
#define W_      31          // windows
#define F_      2220        // GROUPS * SIGC
#define RNN_    256
#define OUT_    10
#define KPAD    2224        // F_ padded to multiple of 16 for guard-free GEMM
#define MROWS   (W_ * B_)   // 3968
#define NGI     768         // 3 * RNN

// ---------------- device scratch (static, allowed) ----------------
__device__ float g_sig[MROWS * KPAD];     // ~35 MB
__device__ float g_Wp [NGI * KPAD];       // padded W_ih copy ~6.8 MB
__device__ float g_gi [MROWS * NGI];      // ~12 MB
__device__ float g_h  [2][B_ * RNN_];     // ping-pong hidden state

// =====================================================================
// Kernel 1: path signatures (Chen, depth 3).
// grid (31, 256): blockIdx.x = window w, blockIdx.y = b*2+g. 128 threads.
// Threads t<100 own (a,b)=(t/10,t%10): S2[a,b] scalar + S3[a,b,:] (10 regs),
// plus a private copy of S1[a]. No barriers in the step loop.
// =====================================================================
__global__ __launch_bounds__(128) void sig_kernel(
    const float* __restrict__ x,       // (128,512,4)
    const float* __restrict__ W_aug)   // (2,5,4)
{
    const int w  = blockIdx.x;
    const int bg = blockIdx.y;
    const int b  = bg >> 1;
    const int g  = bg & 1;
    const int tid = threadIdx.x;

    __shared__ __align__(16) float xs[32][4];
    __shared__ __align__(16) float dxw[31][10];

    // load 32-row x window
    {
        int row = tid >> 2, ch = tid & 3;
        xs[row][ch] = x[(b * STREAM_ + w * STEP_ + row) * INCH + ch];
    }
    __syncthreads();

    // build per-step increments dxw[j][c], c = [x(4), t(1), aug(5)]
    for (int idx = tid; idx < 31 * 10; idx += 128) {
        int j = idx / 10, c = idx % 10;
        float v;
        if (c < 4) {
            v = xs[j + 1][c] - xs[j][c];
        } else if (c == 4) {
            v = 1.0f / 511.0f;                       // linspace(0,1,512) increment
        } else {
            int e = c - 5;
            const float* wa = W_aug + (g * EXTRA_ + e) * INCH;
            v = 0.f;
            #pragma unroll
            for (int i = 0; i < 4; i++) v += wa[i] * (xs[j + 1][i] - xs[j][i]);
        }
        dxw[j][c] = v;
    }
    __syncthreads();

    const size_t base = (size_t)(w * B_ + b) * KPAD + (size_t)g * SIGC;

    if (tid < 100) {
        const int a  = tid / 10;
        const int bb = tid % 10;
        float s1a = 0.f, s2 = 0.f;
        float s3[10];
        #pragma unroll
        for (int c = 0; c < 10; c++) s3[c] = 0.f;

        for (int j = 0; j < 31; j++) {
            float dxa = dxw[j][a];
            float dxb = dxw[j][bb];
            // S3 uses OLD S2, S1:  S3 += (S2 + S1a*dxb/2 + dxa*dxb/6) * dx[c]
            float factor = s2 + dxb * (0.5f * s1a + (1.0f / 6.0f) * dxa);
            #pragma unroll
            for (int c = 0; c < 10; c++) s3[c] += factor * dxw[j][c];
            // S2 uses OLD S1:      S2 += S1a*dxb + dxa*dxb/2
            s2  += dxb * (s1a + 0.5f * dxa);
            s1a += dxa;
        }
        if (bb == 0) g_sig[base + a] = s1a;                 // S1 block (10)
        g_sig[base + 10 + tid] = s2;                        // S2 block (100)
        #pragma unroll
        for (int c = 0; c < 10; c++)                        // S3 block (1000)
            g_sig[base + 110 + tid * 10 + c] = s3[c];
    }
    // zero K-pad columns (once per row; let the g==1 block do it)
    if (g == 1 && tid < (KPAD - F_))
        g_sig[(size_t)(w * B_ + b) * KPAD + F_ + tid] = 0.f;
}

// =====================================================================
// Kernel 2: pad W_ih (768 x 2220) into g_Wp (768 x 2224), zero pad cols
// =====================================================================
__global__ __launch_bounds__(256) void prep_w(const float* __restrict__ Wih)
{
    int idx = blockIdx.x * 256 + threadIdx.x;
    if (idx < NGI * KPAD) {
        int n = idx / KPAD, k = idx - n * KPAD;
        g_Wp[idx] = (k < F_) ? Wih[n * F_ + k] : 0.f;
    }
}

// =====================================================================
// Kernel 3: GI = sig @ W_ih^T + b_ih   (M=3968, N=768, K=2224 padded)
// Classic SIMT SGEMM: 128x128 tile, BK=8, 256 threads, 8x8 microtile.
// =====================================================================
__global__ __launch_bounds__(256) void gemm_gi(const float* __restrict__ bih)
{
    __shared__ __align__(16) float As[8][128];
    __shared__ __align__(16) float Bs[8][128];

    const int m0 = blockIdx.x * 128;
    const int n0 = blockIdx.y * 128;
    const int tid = threadIdx.x;
    const int tx = tid & 15;   // n sub-tile
    const int ty = tid >> 4;   // m sub-tile

    const int lrow = tid >> 1;          // 0..127
    const int lk   = (tid & 1) * 4;     // 0 or 4

    float acc[8][8];
    #pragma unroll
    for (int i = 0; i < 8; i++)
        #pragma unroll
        for (int j = 0; j < 8; j++) acc[i][j] = 0.f;

    const float* Aptr = g_sig + (size_t)(m0 + lrow) * KPAD + lk;
    const float* Bptr = g_Wp  + (size_t)(n0 + lrow) * KPAD + lk;

    for (int k0 = 0; k0 < KPAD; k0 += 8) {
        float4 va = *(const float4*)(Aptr + k0);
        float4 vb = *(const float4*)(Bptr + k0);
        As[lk + 0][lrow] = va.x; As[lk + 1][lrow] = va.y;
        As[lk + 2][lrow] = va.z; As[lk + 3][lrow] = va.w;
        Bs[lk + 0][lrow] = vb.x; Bs[lk + 1][lrow] = vb.y;
        Bs[lk + 2][lrow] = vb.z; Bs[lk + 3][lrow] = vb.w;
        __syncthreads();

        #pragma unroll
        for (int kk = 0; kk < 8; kk++) {
            float4 a0 = *(const float4*)&As[kk][ty * 8];
            float4 a1 = *(const float4*)&As[kk][ty * 8 + 4];
            float4 b0 = *(const float4*)&Bs[kk][tx * 8];
            float4 b1 = *(const float4*)&Bs[kk][tx * 8 + 4];
            float a[8] = {a0.x, a0.y, a0.z, a0.w, a1.x, a1.y, a1.z, a1.w};
            float bv[8] = {b0.x, b0.y, b0.z, b0.w, b1.x, b1.y, b1.z, b1.w};
            #pragma unroll
            for (int i = 0; i < 8; i++)
                #pragma unroll
                for (int j = 0; j < 8; j++) acc[i][j] += a[i] * bv[j];
        }
        __syncthreads();
    }

    // epilogue: add bias, write GI
    float bias[8];
    #pragma unroll
    for (int j = 0; j < 8; j++) bias[j] = bih[n0 + tx * 8 + j];
    #pragma unroll
    for (int i = 0; i < 8; i++) {
        int m = m0 + ty * 8 + i;
        float* dst = g_gi + (size_t)m * NGI + n0 + tx * 8;
        float4 o0, o1;
        o0.x = acc[i][0] + bias[0]; o0.y = acc[i][1] + bias[1];
        o0.z = acc[i][2] + bias[2]; o0.w = acc[i][3] + bias[3];
        o1.x = acc[i][4] + bias[4]; o1.y = acc[i][5] + bias[5];
        o1.z = acc[i][6] + bias[6]; o1.w = acc[i][7] + bias[7];
        *(float4*)(dst)     = o0;
        *(float4*)(dst + 4) = o1;
    }
}

// =====================================================================
// Kernel 4: zero h0
// =====================================================================
__global__ void zero_h()
{
    int i = blockIdx.x * 256 + threadIdx.x;
    if (i < B_ * RNN_) g_h[0][i] = 0.f;
}

// =====================================================================
// Kernel 5: one fused GRU step: gh = h @ W_hh^T + b_hh, gates, new h.
// grid (4, 16): 32-batch tile x 16-gate tile. 256 threads.
// Thread (tx=j-local, ty=b-local) computes 2 batch rows x 1 gate col,
// all 3 gates (r,z,n) in registers.
// =====================================================================
__global__ __launch_bounds__(256) void gru_step(
    int t,
    const float* __restrict__ Whh,   // (768,256)
    const float* __restrict__ bhh)   // (768)
{
    const float* __restrict__ h_in  = g_h[t & 1];
    float*       __restrict__ h_out = g_h[(t + 1) & 1];
    const float* __restrict__ gi_t  = g_gi + (size_t)t * B_ * NGI;

    const int b0 = blockIdx.x * 32;
    const int j0 = blockIdx.y * 16;
    const int tid = threadIdx.x;
    const int tx = tid & 15;   // gate column local
    const int ty = tid >> 4;   // batch local (handles ty and ty+16)

    __shared__ __align__(16) float hs[32][68];
    __shared__ __align__(16) float ws[3][16][68];

    float acc[3][2] = {{0.f, 0.f}, {0.f, 0.f}, {0.f, 0.f}};

    for (int kc = 0; kc < RNN_; kc += 64) {
        for (int i = tid; i < 32 * 16; i += 256) {
            int r = i >> 4, c4 = (i & 15) * 4;
            float4 v = *(const float4*)&h_in[(b0 + r) * RNN_ + kc + c4];
            *(float4*)&hs[r][c4] = v;
        }
        for (int i = tid; i < 48 * 16; i += 256) {
            int r = i >> 4, c4 = (i & 15) * 4;
            int gg = r >> 4, j = r & 15;
            float4 v = *(const float4*)&Whh[(gg * RNN_ + j0 + j) * RNN_ + kc + c4];
            *(float4*)&ws[gg][j][c4] = v;
        }
        __syncthreads();

        #pragma unroll
        for (int k = 0; k < 64; k += 4) {
            float4 h0 = *(const float4*)&hs[ty][k];
            float4 h1 = *(const float4*)&hs[ty + 16][k];
            #pragma unroll
            for (int gg = 0; gg < 3; gg++) {
                float4 wv = *(const float4*)&ws[gg][tx][k];
                acc[gg][0] += wv.x * h0.x + wv.y * h0.y + wv.z * h0.z + wv.w * h0.w;
                acc[gg][1] += wv.x * h1.x + wv.y * h1.y + wv.z * h1.z + wv.w * h1.w;
            }
        }
        __syncthreads();
    }

    const int j = j0 + tx;
    const float br = bhh[j], bz = bhh[RNN_ + j], bn = bhh[2 * RNN_ + j];

    #pragma unroll
    for (int p = 0; p < 2; p++) {
        const int b = b0 + ty + p * 16;
        float hr = acc[0][p] + br;
        float hz = acc[1][p] + bz;
        float hn = acc[2][p] + bn;
        float ir  = gi_t[b * NGI + j];
        float iz  = gi_t[b * NGI + RNN_ + j];
        float inn = gi_t[b * NGI + 2 * RNN_ + j];
        float r = 1.f / (1.f + expf(-(ir + hr)));
        float z = 1.f / (1.f + expf(-(iz + hz)));
        float n = tanhf(inn + r * hn);
        float hprev = h_in[b * RNN_ + j];
        h_out[b * RNN_ + j] = (1.f - z) * n + z * hprev;
    }
}

// =====================================================================
// Kernel 6: output head: sigmoid(h @ W_out^T + b_out). Warp per output.
// =====================================================================
__global__ __launch_bounds__(256) void out_kernel(
    const float* __restrict__ Wout,  // (10,256)
    const float* __restrict__ bout,  // (10)
    float* __restrict__ out)         // (128,10)
{
    const float* __restrict__ h = g_h[1];  // final h after 31 steps (odd)
    int warp = (blockIdx.x * blockDim.x + threadIdx.x) >> 5;
    int lane = threadIdx.x & 31;
    if (warp >= B_ * OUT_) return;
    int b = warp / OUT_, o = warp - b * OUT_;
    float s = 0.f;
    for (int k = lane; k < RNN_; k += 32) s += h[b * RNN_ + k] * Wout[o * RNN_ + k];
    #pragma unroll
    for (int off = 16; off; off >>= 1) s += __shfl_down_sync(0xffffffffu, s, off);
    if (lane == 0) out[b * OUT_ + o] = 1.f / (1.f + expf(-(s + bout[o])));
}

// =====================================================================
extern "C" void kernel_launch(void* const* d_in, const int* in_sizes, int n_in,
                              void* d_out, int out_size)
{
    const float* x     = (const float*)d_in[0];
    const float* W_aug = (const float*)d_in[1];
    // d_in[2] = b_aug: cancels in increments, unused
    const float* W_ih  = (const float*)d_in[3];
    const float* W_hh  = (const float*)d_in[4];
    const float* b_ih  = (const float*)d_in[5];
    const float* b_hh  = (const float*)d_in[6];
    const float* W_out = (const float*)d_in[7];
    const float* b_out = (const float*)d_in[8];
    float* out = (float*)d_out;

    sig_kernel<<<dim3(W_, B_ * G_), 128>>>(x, W_aug);
    prep_w<<<(NGI * KPAD + 255) / 256, 256>>>(W_ih);
    gemm_gi<<<dim3(MROWS / 128, NGI / 128), 256>>>(b_ih);
    zero_h<<<(B_ * RNN_ + 255) / 256, 256>>>();
    for (int t = 0; t < W_; t++)
        gru_step<<<dim3(4, 16), 256>>>(t, W_hh, b_hh);
    out_kernel<<<(B_ * OUT_ * 32 + 255) / 256, 256>>>(W_out, b_out, out);
}

// round 2
// speedup vs baseline: 1.0030x; 1.0030x over previous
#include <cuda_runtime.h>
#include <math.h>

// ---------------- problem constants ----------------
#define B_      128
#define STREAM_ 512
#define INCH    4
#define EXTRA_  5
#define G_      2
#define STEP_   16
#define C_      10          // INCH + 1 + EXTRA
#define SIGC    1110        // C + C^2 + C^3
#define W_      31          // windows
#define F_      2220        // GROUPS * SIGC
#define RNN_    256
#define OUT_    10
#define KPAD    2224        // F_ padded to multiple of 16 for guard-free GEMM
#define MROWS   (W_ * B_)   // 3968
#define NGI     768         // 3 * RNN

// ---------------- device scratch (static, allowed) ----------------
__device__ float g_sig[MROWS * KPAD];     // ~35 MB
__device__ float g_Wp [NGI * KPAD];       // padded W_ih copy ~6.8 MB
__device__ float g_gi [MROWS * NGI];      // ~12 MB
__device__ float g_h  [2][B_ * RNN_];     // ping-pong hidden state

// =====================================================================
// Kernel 1: path signatures (Chen, depth 3).
// grid (31, 256): blockIdx.x = window w, blockIdx.y = b*2+g. 128 threads.
// Threads t<100 own (a,b)=(t/10,t%10): S2[a,b] scalar + S3[a,b,:] (10 regs),
// plus a private copy of S1[a]. No barriers in the step loop.
// =====================================================================
__global__ __launch_bounds__(128) void sig_kernel(
    const float* __restrict__ x,       // (128,512,4)
    const float* __restrict__ W_aug)   // (2,5,4)
{
    const int w  = blockIdx.x;
    const int bg = blockIdx.y;
    const int b  = bg >> 1;
    const int g  = bg & 1;
    const int tid = threadIdx.x;

    __shared__ __align__(16) float xs[32][4];
    __shared__ __align__(16) float dxw[31][10];

    // load 32-row x window
    {
        int row = tid >> 2, ch = tid & 3;
        xs[row][ch] = x[(b * STREAM_ + w * STEP_ + row) * INCH + ch];
    }
    __syncthreads();

    // build per-step increments dxw[j][c], c = [x(4), t(1), aug(5)]
    for (int idx = tid; idx < 31 * 10; idx += 128) {
        int j = idx / 10, c = idx % 10;
        float v;
        if (c < 4) {
            v = xs[j + 1][c] - xs[j][c];
        } else if (c == 4) {
            v = 1.0f / 511.0f;                       // linspace(0,1,512) increment
        } else {
            int e = c - 5;
            const float* wa = W_aug + (g * EXTRA_ + e) * INCH;
            v = 0.f;
            #pragma unroll
            for (int i = 0; i < 4; i++) v += wa[i] * (xs[j + 1][i] - xs[j][i]);
        }
        dxw[j][c] = v;
    }
    __syncthreads();

    const size_t base = (size_t)(w * B_ + b) * KPAD + (size_t)g * SIGC;

    if (tid < 100) {
        const int a  = tid / 10;
        const int bb = tid % 10;
        float s1a = 0.f, s2 = 0.f;
        float s3[10];
        #pragma unroll
        for (int c = 0; c < 10; c++) s3[c] = 0.f;

        for (int j = 0; j < 31; j++) {
            float dxa = dxw[j][a];
            float dxb = dxw[j][bb];
            // S3 uses OLD S2, S1:  S3 += (S2 + S1a*dxb/2 + dxa*dxb/6) * dx[c]
            float factor = s2 + dxb * (0.5f * s1a + (1.0f / 6.0f) * dxa);
            #pragma unroll
            for (int c = 0; c < 10; c++) s3[c] += factor * dxw[j][c];
            // S2 uses OLD S1:      S2 += S1a*dxb + dxa*dxb/2
            s2  += dxb * (s1a + 0.5f * dxa);
            s1a += dxa;
        }
        if (bb == 0) g_sig[base + a] = s1a;                 // S1 block (10)
        g_sig[base + 10 + tid] = s2;                        // S2 block (100)
        #pragma unroll
        for (int c = 0; c < 10; c++)                        // S3 block (1000)
            g_sig[base + 110 + tid * 10 + c] = s3[c];
    }
    // zero K-pad columns (once per row; let the g==1 block do it)
    if (g == 1 && tid < (KPAD - F_))
        g_sig[(size_t)(w * B_ + b) * KPAD + F_ + tid] = 0.f;
}

// =====================================================================
// Kernel 2: pad W_ih (768 x 2220) into g_Wp (768 x 2224), zero pad cols
// =====================================================================
__global__ __launch_bounds__(256) void prep_w(const float* __restrict__ Wih)
{
    int idx = blockIdx.x * 256 + threadIdx.x;
    if (idx < NGI * KPAD) {
        int n = idx / KPAD, k = idx - n * KPAD;
        g_Wp[idx] = (k < F_) ? Wih[n * F_ + k] : 0.f;
    }
}

// =====================================================================
// Kernel 3: GI = sig @ W_ih^T + b_ih   (M=3968, N=768, K=2224 padded)
// Classic SIMT SGEMM: 128x128 tile, BK=8, 256 threads, 8x8 microtile.
// =====================================================================
__global__ __launch_bounds__(256) void gemm_gi(const float* __restrict__ bih)
{
    __shared__ __align__(16) float As[8][128];
    __shared__ __align__(16) float Bs[8][128];

    const int m0 = blockIdx.x * 128;
    const int n0 = blockIdx.y * 128;
    const int tid = threadIdx.x;
    const int tx = tid & 15;   // n sub-tile
    const int ty = tid >> 4;   // m sub-tile

    const int lrow = tid >> 1;          // 0..127
    const int lk   = (tid & 1) * 4;     // 0 or 4

    float acc[8][8];
    #pragma unroll
    for (int i = 0; i < 8; i++)
        #pragma unroll
        for (int j = 0; j < 8; j++) acc[i][j] = 0.f;

    const float* Aptr = g_sig + (size_t)(m0 + lrow) * KPAD + lk;
    const float* Bptr = g_Wp  + (size_t)(n0 + lrow) * KPAD + lk;

    for (int k0 = 0; k0 < KPAD; k0 += 8) {
        float4 va = *(const float4*)(Aptr + k0);
        float4 vb = *(const float4*)(Bptr + k0);
        As[lk + 0][lrow] = va.x; As[lk + 1][lrow] = va.y;
        As[lk + 2][lrow] = va.z; As[lk + 3][lrow] = va.w;
        Bs[lk + 0][lrow] = vb.x; Bs[lk + 1][lrow] = vb.y;
        Bs[lk + 2][lrow] = vb.z; Bs[lk + 3][lrow] = vb.w;
        __syncthreads();

        #pragma unroll
        for (int kk = 0; kk < 8; kk++) {
            float4 a0 = *(const float4*)&As[kk][ty * 8];
            float4 a1 = *(const float4*)&As[kk][ty * 8 + 4];
            float4 b0 = *(const float4*)&Bs[kk][tx * 8];
            float4 b1 = *(const float4*)&Bs[kk][tx * 8 + 4];
            float a[8] = {a0.x, a0.y, a0.z, a0.w, a1.x, a1.y, a1.z, a1.w};
            float bv[8] = {b0.x, b0.y, b0.z, b0.w, b1.x, b1.y, b1.z, b1.w};
            #pragma unroll
            for (int i = 0; i < 8; i++)
                #pragma unroll
                for (int j = 0; j < 8; j++) acc[i][j] += a[i] * bv[j];
        }
        __syncthreads();
    }

    // epilogue: add bias, write GI
    float bias[8];
    #pragma unroll
    for (int j = 0; j < 8; j++) bias[j] = bih[n0 + tx * 8 + j];
    #pragma unroll
    for (int i = 0; i < 8; i++) {
        int m = m0 + ty * 8 + i;
        float* dst = g_gi + (size_t)m * NGI + n0 + tx * 8;
        float4 o0, o1;
        o0.x = acc[i][0] + bias[0]; o0.y = acc[i][1] + bias[1];
        o0.z = acc[i][2] + bias[2]; o0.w = acc[i][3] + bias[3];
        o1.x = acc[i][4] + bias[4]; o1.y = acc[i][5] + bias[5];
        o1.z = acc[i][6] + bias[6]; o1.w = acc[i][7] + bias[7];
        *(float4*)(dst)     = o0;
        *(float4*)(dst + 4) = o1;
    }
}

// =====================================================================
// Kernel 4: zero h0
// =====================================================================
__global__ void zero_h()
{
    int i = blockIdx.x * 256 + threadIdx.x;
    if (i < B_ * RNN_) g_h[0][i] = 0.f;
}

// =====================================================================
// Kernel 5: one fused GRU step: gh = h @ W_hh^T + b_hh, gates, new h.
// grid (4, 16): 32-batch tile x 16-gate tile. 256 threads.
// Thread (tx=j-local, ty=b-local) computes 2 batch rows x 1 gate col,
// all 3 gates (r,z,n) in registers.
// =====================================================================
__global__ __launch_bounds__(256) void gru_step(
    int t,
    const float* __restrict__ Whh,   // (768,256)
    const float* __restrict__ bhh)   // (768)
{
    const float* __restrict__ h_in  = g_h[t & 1];
    float*       __restrict__ h_out = g_h[(t + 1) & 1];
    const float* __restrict__ gi_t  = g_gi + (size_t)t * B_ * NGI;

    const int b0 = blockIdx.x * 32;
    const int j0 = blockIdx.y * 16;
    const int tid = threadIdx.x;
    const int tx = tid & 15;   // gate column local
    const int ty = tid >> 4;   // batch local (handles ty and ty+16)

    __shared__ __align__(16) float hs[32][68];
    __shared__ __align__(16) float ws[3][16][68];

    float acc[3][2] = {{0.f, 0.f}, {0.f, 0.f}, {0.f, 0.f}};

    for (int kc = 0; kc < RNN_; kc += 64) {
        for (int i = tid; i < 32 * 16; i += 256) {
            int r = i >> 4, c4 = (i & 15) * 4;
            float4 v = *(const float4*)&h_in[(b0 + r) * RNN_ + kc + c4];
            *(float4*)&hs[r][c4] = v;
        }
        for (int i = tid; i < 48 * 16; i += 256) {
            int r = i >> 4, c4 = (i & 15) * 4;
            int gg = r >> 4, j = r & 15;
            float4 v = *(const float4*)&Whh[(gg * RNN_ + j0 + j) * RNN_ + kc + c4];
            *(float4*)&ws[gg][j][c4] = v;
        }
        __syncthreads();

        #pragma unroll
        for (int k = 0; k < 64; k += 4) {
            float4 h0 = *(const float4*)&hs[ty][k];
            float4 h1 = *(const float4*)&hs[ty + 16][k];
            #pragma unroll
            for (int gg = 0; gg < 3; gg++) {
                float4 wv = *(const float4*)&ws[gg][tx][k];
                acc[gg][0] += wv.x * h0.x + wv.y * h0.y + wv.z * h0.z + wv.w * h0.w;
                acc[gg][1] += wv.x * h1.x + wv.y * h1.y + wv.z * h1.z + wv.w * h1.w;
            }
        }
        __syncthreads();
    }

    const int j = j0 + tx;
    const float br = bhh[j], bz = bhh[RNN_ + j], bn = bhh[2 * RNN_ + j];

    #pragma unroll
    for (int p = 0; p < 2; p++) {
        const int b = b0 + ty + p * 16;
        float hr = acc[0][p] + br;
        float hz = acc[1][p] + bz;
        float hn = acc[2][p] + bn;
        float ir  = gi_t[b * NGI + j];
        float iz  = gi_t[b * NGI + RNN_ + j];
        float inn = gi_t[b * NGI + 2 * RNN_ + j];
        float r = 1.f / (1.f + expf(-(ir + hr)));
        float z = 1.f / (1.f + expf(-(iz + hz)));
        float n = tanhf(inn + r * hn);
        float hprev = h_in[b * RNN_ + j];
        h_out[b * RNN_ + j] = (1.f - z) * n + z * hprev;
    }
}

// =====================================================================
// Kernel 6: output head: sigmoid(h @ W_out^T + b_out). Warp per output.
// =====================================================================
__global__ __launch_bounds__(256) void out_kernel(
    const float* __restrict__ Wout,  // (10,256)
    const float* __restrict__ bout,  // (10)
    float* __restrict__ out)         // (128,10)
{
    const float* __restrict__ h = g_h[1];  // final h after 31 steps (odd)
    int warp = (blockIdx.x * blockDim.x + threadIdx.x) >> 5;
    int lane = threadIdx.x & 31;
    if (warp >= B_ * OUT_) return;
    int b = warp / OUT_, o = warp - b * OUT_;
    float s = 0.f;
    for (int k = lane; k < RNN_; k += 32) s += h[b * RNN_ + k] * Wout[o * RNN_ + k];
    #pragma unroll
    for (int off = 16; off; off >>= 1) s += __shfl_down_sync(0xffffffffu, s, off);
    if (lane == 0) out[b * OUT_ + o] = 1.f / (1.f + expf(-(s + bout[o])));
}

// =====================================================================
extern "C" void kernel_launch(void* const* d_in, const int* in_sizes, int n_in,
                              void* d_out, int out_size)
{
    const float* x     = (const float*)d_in[0];
    const float* W_aug = (const float*)d_in[1];
    // d_in[2] = b_aug: cancels in increments, unused
    const float* W_ih  = (const float*)d_in[3];
    const float* W_hh  = (const float*)d_in[4];
    const float* b_ih  = (const float*)d_in[5];
    const float* b_hh  = (const float*)d_in[6];
    const float* W_out = (const float*)d_in[7];
    const float* b_out = (const float*)d_in[8];
    float* out = (float*)d_out;

    sig_kernel<<<dim3(W_, B_ * G_), 128>>>(x, W_aug);
    prep_w<<<(NGI * KPAD + 255) / 256, 256>>>(W_ih);
    gemm_gi<<<dim3(MROWS / 128, NGI / 128), 256>>>(b_ih);
    zero_h<<<(B_ * RNN_ + 255) / 256, 256>>>();
    for (int t = 0; t < W_; t++)
        gru_step<<<dim3(4, 16), 256>>>(t, W_hh, b_hh);
    out_kernel<<<(B_ * OUT_ * 32 + 255) / 256, 256>>>(W_out, b_out, out);
}